// round 8
// baseline (speedup 1.0000x reference)
#include <cuda_runtime.h>

typedef unsigned long long u64;

#define NB 1024
#define SL 512
#define NL 64

__device__ __forceinline__ u64 fma2(u64 a, u64 b, u64 c) {
    u64 d;
    asm("fma.rn.f32x2 %0, %1, %2, %3;" : "=l"(d) : "l"(a), "l"(b), "l"(c));
    return d;
}
__device__ __forceinline__ u64 add2(u64 a, u64 b) {
    u64 d;
    asm("add.rn.f32x2 %0, %1, %2;" : "=l"(d) : "l"(a), "l"(b));
    return d;
}
__device__ __forceinline__ u64 pack2(float lo, float hi) {
    u64 d;
    asm("mov.b64 %0, {%1, %2};" : "=l"(d) : "f"(lo), "f"(hi));
    return d;
}
__device__ __forceinline__ void unpack2(u64 a, float& lo, float& hi) {
    asm("mov.b64 {%0, %1}, %2;" : "=f"(lo), "=f"(hi) : "l"(a));
}

// 128-thread CTA = FOUR warps = four independent batches (warp w owns batch
// 4*blockIdx+w). SMSP = wid%4, so 4-warp CTAs engage ALL FOUR schedulers —
// every previous round's 64/32-thread blocks left SMSP 2/3 idle.
//
// Per warp (R7 layout): lane l owns columns (2l, 2l+1); 16 LDS.128 +
// 64 fma2 per batch-step, 8 accumulators (chain depth 8). __syncwarp only.
//
// Multiplicative recurrence (exact for any scalar C):
//   s_j = sum_i q_i E_ij ; q'_j = s_j * exp(em_j - C) ; Z += C
// C_{t+1} = em_0^{t+1} + n*ln2, n = exponent(q_0): pure ALU, lane-0 register
// + one __shfl. Mask handled with selects only.
__global__ __launch_bounds__(128) void crf_fwd_kernel(
    const float* __restrict__ emissions,
    const int*   __restrict__ mask,
    const float* __restrict__ trans,
    const float* __restrict__ startt,
    const float* __restrict__ endt,
    float* __restrict__ out)
{
    __shared__ __align__(16) float qbuf[4][2][NL];   // [warp][buf][label]

    const int tid = threadIdx.x;
    const int w   = tid >> 5;
    const int l   = tid & 31;
    const int b   = blockIdx.x * 4 + w;
    const size_t ebase = (size_t)b * SL * NL;
    const int ca = 2 * l;
    const int cb = 2 * l + 1;
    const unsigned FULL = 0xffffffffu;

    // E columns ca/cb, packed over adjacent row pairs (rows 2m, 2m+1).
    u64 Ea[32], Eb[32];
#pragma unroll
    for (int m = 0; m < 32; m++) {
        Ea[m] = pack2(__expf(trans[(2 * m) * NL + ca]),
                      __expf(trans[(2 * m + 1) * NL + ca]));
        Eb[m] = pack2(__expf(trans[(2 * m) * NL + cb]),
                      __expf(trans[(2 * m + 1) * NL + cb]));
    }
    const float fend_a = __expf(endt[ca]);
    const float fend_b = __expf(endt[cb]);
    const float LN2 = 0.6931471805599453f;

    // t = 0: normalize by score of label 0 -> q_0 = 1.
    float2 e0 = *(const float2*)&emissions[ebase + ca];
    float sc_a = startt[ca] + e0.x;
    float sc_b = startt[cb] + e0.y;
    const float z0 = __shfl_sync(FULL, sc_a, 0);
    float qa = __expf(sc_a - z0);
    float qb = __expf(sc_b - z0);
    float Z = z0;
    *(float2*)&qbuf[w][0][ca] = make_float2(qa, qb);

    // prefetch t = 1
    float2 em_n = *(const float2*)&emissions[ebase + NL + ca];
    int    mk_n = mask[b * SL + 1];
    float  Cn = em_n.x;                 // lane 0: C_1 = em_0^1 (q_0 = 1)

#pragma unroll 2
    for (int t = 1; t < SL; t++) {
        __syncwarp(FULL);               // publishes qbuf[w][pb]
        const int pb  = (t - 1) & 1;
        const int cbf = t & 1;
        const float C   = __shfl_sync(FULL, Cn, 0);
        const float ema = em_n.x, emb = em_n.y;
        const int   mk  = mk_n;

        const int tn = (t + 1 < SL) ? t + 1 : SL - 1;
        em_n = *(const float2*)&emissions[ebase + (size_t)tn * NL + ca];
        mk_n = mask[b * SL + tn];

        // hidden under the LDS + FMA tree
        const float cfa = __expf(ema - C);
        const float cfb = __expf(emb - C);

        // full matvec for both owned columns, 8 accumulators (depth 8)
        const ulonglong2* qp = (const ulonglong2*)qbuf[w][pb];
        u64 a0 = 0, a1 = 0, a2 = 0, a3 = 0;
        u64 c0 = 0, c1 = 0, c2 = 0, c3 = 0;
#pragma unroll
        for (int k = 0; k < 8; k++) {
            ulonglong2 v0 = qp[2 * k];
            ulonglong2 v1 = qp[2 * k + 1];
            a0 = fma2(v0.x, Ea[4 * k + 0], a0);  c0 = fma2(v0.x, Eb[4 * k + 0], c0);
            a1 = fma2(v0.y, Ea[4 * k + 1], a1);  c1 = fma2(v0.y, Eb[4 * k + 1], c1);
            a2 = fma2(v1.x, Ea[4 * k + 2], a2);  c2 = fma2(v1.x, Eb[4 * k + 2], c2);
            a3 = fma2(v1.y, Ea[4 * k + 3], a3);  c3 = fma2(v1.y, Eb[4 * k + 3], c3);
        }
        float xa, ya, xb, yb;
        unpack2(add2(add2(a0, a1), add2(a2, a3)), xa, ya);
        unpack2(add2(add2(c0, c1), add2(c2, c3)), xb, yb);
        const float sa = xa + ya;
        const float sb = xb + yb;

        // branchless mask
        const float qna = sa * cfa;
        const float qnb = sb * cfb;
        const float Zp  = Z + C;
        qa = mk ? qna : qa;
        qb = mk ? qnb : qb;
        Z  = mk ? Zp  : Z;
        *(float2*)&qbuf[w][cbf][ca] = make_float2(qa, qb);

        // next normalizer (valid on lane 0, broadcast next iter)
        const int n = (int)(__float_as_uint(qa) >> 23) - 127;
        Cn = fmaf((float)n, LN2, em_n.x);
    }

    // out[b] = Z + ln( sum_j q_j * exp(end_j) )
    float v = qa * fend_a + qb * fend_b;
#pragma unroll
    for (int o = 16; o; o >>= 1) v += __shfl_xor_sync(FULL, v, o);
    if (l == 0) out[b] = Z + __logf(v);
}

extern "C" void kernel_launch(void* const* d_in, const int* in_sizes, int n_in,
                              void* d_out, int out_size) {
    const float* emissions = (const float*)d_in[0];
    const int*   msk       = (const int*)d_in[1];
    const float* trans     = (const float*)d_in[2];
    const float* startt    = (const float*)d_in[3];
    const float* endt      = (const float*)d_in[4];
    crf_fwd_kernel<<<NB / 4, 128>>>(emissions, msk, trans, startt, endt, (float*)d_out);
}

// round 10
// speedup vs baseline: 1.9121x; 1.9121x over previous
#include <cuda_runtime.h>

typedef unsigned long long u64;

#define NB 1024
#define SL 512
#define NL 64

__device__ __forceinline__ u64 fma2(u64 a, u64 b, u64 c) {
    u64 d;
    asm("fma.rn.f32x2 %0, %1, %2, %3;" : "=l"(d) : "l"(a), "l"(b), "l"(c));
    return d;
}
__device__ __forceinline__ u64 add2(u64 a, u64 b) {
    u64 d;
    asm("add.rn.f32x2 %0, %1, %2;" : "=l"(d) : "l"(a), "l"(b));
    return d;
}
__device__ __forceinline__ u64 pack2(float lo, float hi) {
    u64 d;
    asm("mov.b64 %0, {%1, %2};" : "=l"(d) : "f"(lo), "f"(hi));
    return d;
}
__device__ __forceinline__ void unpack2(u64 a, float& lo, float& hi) {
    asm("mov.b64 {%0, %1}, %2;" : "=f"(lo), "=f"(hi) : "l"(a));
}

// R7 structure (proven 232us / rel 3.6e-7): 64-thread CTA = 2 warps = 2
// batches; lane l owns columns (2l, 2l+1); 16 LDS.128 + 64 fma2 per step.
//
// NEW vs R7: time-unroll x4 with the next group's emissions (4x LDG.64) and
// int4 mask prefetched a full group ahead (MLP=5) — removes the ~830-cycle
// 1-step-ahead DRAM wait that R1==R7 timing implicated as the binding chain.
// Normalizer C re-anchored EVERY step (R9's 4-step-constant anchor drifted
// past the exp overflow threshold -> NaN): drift <= ~28 << 88, safe.
#define STEP(PB, CBF, EMA, EMB, MK) do {                                      \
    __syncwarp(FULL);                                                          \
    const float cfa = __expf((EMA) - C);                                       \
    const float cfb = __expf((EMB) - C);                                       \
    const ulonglong2* qp = (const ulonglong2*)qbuf[w][(PB)];                   \
    u64 a0 = 0, a1 = 0, c0 = 0, c1 = 0;                                        \
    _Pragma("unroll")                                                          \
    for (int k = 0; k < 8; k++) {                                              \
        ulonglong2 v0 = qp[2 * k];                                             \
        ulonglong2 v1 = qp[2 * k + 1];                                         \
        a0 = fma2(v0.x, Ea[4 * k + 0], a0);  c0 = fma2(v0.x, Eb[4 * k + 0], c0);\
        a1 = fma2(v0.y, Ea[4 * k + 1], a1);  c1 = fma2(v0.y, Eb[4 * k + 1], c1);\
        a0 = fma2(v1.x, Ea[4 * k + 2], a0);  c0 = fma2(v1.x, Eb[4 * k + 2], c0);\
        a1 = fma2(v1.y, Ea[4 * k + 3], a1);  c1 = fma2(v1.y, Eb[4 * k + 3], c1);\
    }                                                                          \
    float xa, ya, xb, yb;                                                      \
    unpack2(add2(a0, a1), xa, ya);                                             \
    unpack2(add2(c0, c1), xb, yb);                                             \
    const float sa = xa + ya;                                                  \
    const float sb = xb + yb;                                                  \
    qa = (MK) ? sa * cfa : qa;                                                 \
    qb = (MK) ? sb * cfb : qb;                                                 \
    Z  = (MK) ? Z + C    : Z;                                                  \
    *(float2*)&qbuf[w][(CBF)][ca] = make_float2(qa, qb);                       \
} while (0)

// per-step re-anchor: C' = ilogb(q_0)*ln2 + em_0^{next} (lane 0 broadcast)
#define CUPD(NEXT_EM) do {                                                    \
    const int n = (int)(__float_as_uint(qa) >> 23) - 127;                      \
    C = __shfl_sync(FULL, fmaf((float)n, LN2, (NEXT_EM)), 0);                  \
} while (0)

__global__ __launch_bounds__(64) void crf_fwd_kernel(
    const float* __restrict__ emissions,
    const int*   __restrict__ mask,
    const float* __restrict__ trans,
    const float* __restrict__ startt,
    const float* __restrict__ endt,
    float* __restrict__ out)
{
    __shared__ __align__(16) float qbuf[2][2][NL];   // [warp][buf][label]

    const int tid = threadIdx.x;
    const int w   = tid >> 5;
    const int l   = tid & 31;
    const int b   = blockIdx.x * 2 + w;
    const size_t ebase = (size_t)b * SL * NL;
    const int ca = 2 * l;
    const int cb = 2 * l + 1;
    const unsigned FULL = 0xffffffffu;
    const float LN2 = 0.6931471805599453f;

    // E columns ca/cb, packed over adjacent row pairs (rows 2m, 2m+1).
    u64 Ea[32], Eb[32];
#pragma unroll
    for (int m = 0; m < 32; m++) {
        Ea[m] = pack2(__expf(trans[(2 * m) * NL + ca]),
                      __expf(trans[(2 * m + 1) * NL + ca]));
        Eb[m] = pack2(__expf(trans[(2 * m) * NL + cb]),
                      __expf(trans[(2 * m + 1) * NL + cb]));
    }
    const float fend_a = __expf(endt[ca]);
    const float fend_b = __expf(endt[cb]);

    // upfront prefetch: t=0..7 emissions pieces + masks (MLP ~ 9)
    float2 e0  = *(const float2*)&emissions[ebase + (size_t)0 * NL + ca];
    float2 em1 = *(const float2*)&emissions[ebase + (size_t)1 * NL + ca];
    float2 em2 = *(const float2*)&emissions[ebase + (size_t)2 * NL + ca];
    float2 em3 = *(const float2*)&emissions[ebase + (size_t)3 * NL + ca];
    float2 eb0 = *(const float2*)&emissions[ebase + (size_t)4 * NL + ca];
    float2 eb1 = *(const float2*)&emissions[ebase + (size_t)5 * NL + ca];
    float2 eb2 = *(const float2*)&emissions[ebase + (size_t)6 * NL + ca];
    float2 eb3 = *(const float2*)&emissions[ebase + (size_t)7 * NL + ca];
    const int4 m0 = *(const int4*)&mask[b * SL];      // .y,.z,.w -> t=1,2,3
    int4 mv = *(const int4*)&mask[b * SL + 4];        // t=4..7

    // t = 0: normalize by score of label 0 -> q_0 = 1 exactly.
    float sc_a = startt[ca] + e0.x;
    float sc_b = startt[cb] + e0.y;
    const float z0 = __shfl_sync(FULL, sc_a, 0);
    float qa = __expf(sc_a - z0);
    float qb = __expf(sc_b - z0);
    float Z = z0;
    *(float2*)&qbuf[w][0][ca] = make_float2(qa, qb);

    float C = __shfl_sync(FULL, em1.x, 0);    // C_1 = em_0^1 (q_0 = 1, n = 0)

    // prologue: t = 1..3
    STEP(0, 1, em1.x, em1.y, m0.y);  CUPD(em2.x);
    STEP(1, 0, em2.x, em2.y, m0.z);  CUPD(em3.x);
    STEP(0, 1, em3.x, em3.y, m0.w);  CUPD(eb0.x);

    // main loop: groups of 4, next group prefetched at group top (MLP=5)
#pragma unroll 1
    for (int t0 = 4; t0 < SL; t0 += 4) {
        const int tn0 = (t0 + 4 < SL) ? t0 + 4 : SL - 4;   // clamp: C is an
        const float2 nb0 = *(const float2*)&emissions[ebase + (size_t)(tn0    ) * NL + ca];
        const float2 nb1 = *(const float2*)&emissions[ebase + (size_t)(tn0 + 1) * NL + ca];
        const float2 nb2 = *(const float2*)&emissions[ebase + (size_t)(tn0 + 2) * NL + ca];
        const float2 nb3 = *(const float2*)&emissions[ebase + (size_t)(tn0 + 3) * NL + ca];
        const int4   nmv = *(const int4*)&mask[b * SL + tn0];   // arbitrary-C-safe

        STEP(1, 0, eb0.x, eb0.y, mv.x);  CUPD(eb1.x);
        STEP(0, 1, eb1.x, eb1.y, mv.y);  CUPD(eb2.x);
        STEP(1, 0, eb2.x, eb2.y, mv.z);  CUPD(eb3.x);
        STEP(0, 1, eb3.x, eb3.y, mv.w);  CUPD(nb0.x);

        eb0 = nb0; eb1 = nb1; eb2 = nb2; eb3 = nb3; mv = nmv;
    }

    // out[b] = Z + ln( sum_j q_j * exp(end_j) )
    float v = qa * fend_a + qb * fend_b;
#pragma unroll
    for (int o = 16; o; o >>= 1) v += __shfl_xor_sync(FULL, v, o);
    if (l == 0) out[b] = Z + __logf(v);
}

extern "C" void kernel_launch(void* const* d_in, const int* in_sizes, int n_in,
                              void* d_out, int out_size) {
    const float* emissions = (const float*)d_in[0];
    const int*   msk       = (const int*)d_in[1];
    const float* trans     = (const float*)d_in[2];
    const float* startt    = (const float*)d_in[3];
    const float* endt      = (const float*)d_in[4];
    crf_fwd_kernel<<<NB / 2, 64>>>(emissions, msk, trans, startt, endt, (float*)d_out);
}

// round 11
// speedup vs baseline: 2.6010x; 1.3603x over previous
#include <cuda_runtime.h>

typedef unsigned long long u64;

#define NB 1024
#define SL 512
#define NL 64

__device__ __forceinline__ u64 fma2(u64 a, u64 b, u64 c) {
    u64 d;
    asm("fma.rn.f32x2 %0, %1, %2, %3;" : "=l"(d) : "l"(a), "l"(b), "l"(c));
    return d;
}
__device__ __forceinline__ u64 add2(u64 a, u64 b) {
    u64 d;
    asm("add.rn.f32x2 %0, %1, %2;" : "=l"(d) : "l"(a), "l"(b));
    return d;
}
__device__ __forceinline__ u64 pack2(float lo, float hi) {
    u64 d;
    asm("mov.b64 %0, {%1, %2};" : "=l"(d) : "f"(lo), "f"(hi));
    return d;
}
__device__ __forceinline__ void unpack2(u64 a, float& lo, float& hi) {
    asm("mov.b64 {%0, %1}, %2;" : "=f"(lo), "=f"(hi) : "l"(a));
}

// MUFU-free exp2: magic round + degree-4 Taylor + exponent splice.
// |t| <= ~70 in this kernel; rel err <= ~4.5e-5, near-zero-mean.
__device__ __forceinline__ float fexp2(float t) {
    const float MAGIC = 12582912.0f;            // 1.5 * 2^23
    const float r  = t + MAGIC;                 // RN -> integer in mantissa
    const float fn = r - MAGIC;                 // rounded n as float
    const float f  = t - fn;                    // f in [-0.5, 0.5]
    float p = 0.0096181f;
    p = fmaf(p, f, 0.0555042f);
    p = fmaf(p, f, 0.2402265f);
    p = fmaf(p, f, 0.6931472f);
    p = fmaf(p, f, 1.0f);
    // (bits(r) << 23) == n << 23 (high bits of the magic shift out mod 2^32)
    return __uint_as_float(__float_as_uint(p) + (__float_as_uint(r) << 23));
}

// R10 structure (proven 202us / rel 3.6e-7): 64-thread CTA = 2 warps = 2
// batches; lane l owns columns (2l, 2l+1); 16 LDS.128 + 64 fma2 per step;
// time-unroll x4 with group prefetch (MLP=5); per-step re-anchored scalar
// normalizer. ONLY change vs R10: hot-loop __expf (MUFU.EX2 — the hidden
// binding pipe: 64 MUFU/warp-step ~ 1024 cyc/SMSP/step-round at rt8) is
// replaced by fexp2 on the fma/alu pipes, with everything carried in the
// log2 domain (emissions pre-scaled by log2e at prefetch, off-chain).
#define STEP(PB, CBF, EMA, EMB, MK) do {                                      \
    __syncwarp(FULL);                                                          \
    const float cfa = fexp2((EMA) - C2);                                       \
    const float cfb = fexp2((EMB) - C2);                                       \
    const ulonglong2* qp = (const ulonglong2*)qbuf[w][(PB)];                   \
    u64 a0 = 0, a1 = 0, c0 = 0, c1 = 0;                                        \
    _Pragma("unroll")                                                          \
    for (int k = 0; k < 8; k++) {                                              \
        ulonglong2 v0 = qp[2 * k];                                             \
        ulonglong2 v1 = qp[2 * k + 1];                                         \
        a0 = fma2(v0.x, Ea[4 * k + 0], a0);  c0 = fma2(v0.x, Eb[4 * k + 0], c0);\
        a1 = fma2(v0.y, Ea[4 * k + 1], a1);  c1 = fma2(v0.y, Eb[4 * k + 1], c1);\
        a0 = fma2(v1.x, Ea[4 * k + 2], a0);  c0 = fma2(v1.x, Eb[4 * k + 2], c0);\
        a1 = fma2(v1.y, Ea[4 * k + 3], a1);  c1 = fma2(v1.y, Eb[4 * k + 3], c1);\
    }                                                                          \
    float xa, ya, xb, yb;                                                      \
    unpack2(add2(a0, a1), xa, ya);                                             \
    unpack2(add2(c0, c1), xb, yb);                                             \
    const float sa = xa + ya;                                                  \
    const float sb = xb + yb;                                                  \
    qa = (MK) ? sa * cfa : qa;                                                 \
    qb = (MK) ? sb * cfb : qb;                                                 \
    Z2 = (MK) ? Z2 + C2  : Z2;                                                 \
    *(float2*)&qbuf[w][(CBF)][ca] = make_float2(qa, qb);                       \
} while (0)

// re-anchor in log2 domain: C2' = exponent(q_0) + e2_0^{next} (lane 0 bcast)
// (n * ln2 * log2e == n — no I2F-heavy scaling needed beyond the int cast)
#define CUPD(NEXT_E2) do {                                                    \
    const int n = (int)(__float_as_uint(qa) >> 23) - 127;                      \
    C2 = __shfl_sync(FULL, (float)n + (NEXT_E2), 0);                           \
} while (0)

__global__ __launch_bounds__(64) void crf_fwd_kernel(
    const float* __restrict__ emissions,
    const int*   __restrict__ mask,
    const float* __restrict__ trans,
    const float* __restrict__ startt,
    const float* __restrict__ endt,
    float* __restrict__ out)
{
    __shared__ __align__(16) float qbuf[2][2][NL];   // [warp][buf][label]

    const int tid = threadIdx.x;
    const int w   = tid >> 5;
    const int l   = tid & 31;
    const int b   = blockIdx.x * 2 + w;
    const size_t ebase = (size_t)b * SL * NL;
    const int ca = 2 * l;
    const int cb = 2 * l + 1;
    const unsigned FULL = 0xffffffffu;
    const float LN2 = 0.6931471805599453f;
    const float L2E = 1.4426950408889634f;

    // E columns ca/cb, packed over adjacent row pairs (rows 2m, 2m+1).
    u64 Ea[32], Eb[32];
#pragma unroll
    for (int m = 0; m < 32; m++) {
        Ea[m] = pack2(__expf(trans[(2 * m) * NL + ca]),
                      __expf(trans[(2 * m + 1) * NL + ca]));
        Eb[m] = pack2(__expf(trans[(2 * m) * NL + cb]),
                      __expf(trans[(2 * m + 1) * NL + cb]));
    }
    const float fend_a = __expf(endt[ca]);
    const float fend_b = __expf(endt[cb]);

    // scale to log2 domain at load (off-chain FMULs)
#define LD2(T) make_float2(L2E * (*(const float2*)&emissions[ebase + (size_t)(T) * NL + ca]).x, \
                           L2E * (*(const float2*)&emissions[ebase + (size_t)(T) * NL + ca]).y)

    // upfront prefetch: t=0..7 emissions (log2-scaled) + masks
    float2 e0  = *(const float2*)&emissions[ebase + (size_t)0 * NL + ca];
    float2 em1 = LD2(1);
    float2 em2 = LD2(2);
    float2 em3 = LD2(3);
    float2 eb0 = LD2(4);
    float2 eb1 = LD2(5);
    float2 eb2 = LD2(6);
    float2 eb3 = LD2(7);
    const int4 m0 = *(const int4*)&mask[b * SL];      // .y,.z,.w -> t=1,2,3
    int4 mv = *(const int4*)&mask[b * SL + 4];        // t=4..7

    // t = 0: normalize by score of label 0 -> q_0 = 1 exactly.
    float sc_a = startt[ca] + e0.x;
    float sc_b = startt[cb] + e0.y;
    const float z0 = __shfl_sync(FULL, sc_a, 0);
    float qa = __expf(sc_a - z0);
    float qb = __expf(sc_b - z0);
    float Z2 = z0 * L2E;                       // log2-domain accumulator
    *(float2*)&qbuf[w][0][ca] = make_float2(qa, qb);

    float C2 = __shfl_sync(FULL, em1.x, 0);    // C2_1 = e2_0^1 (q_0 = 1, n = 0)

    // prologue: t = 1..3
    STEP(0, 1, em1.x, em1.y, m0.y);  CUPD(em2.x);
    STEP(1, 0, em2.x, em2.y, m0.z);  CUPD(em3.x);
    STEP(0, 1, em3.x, em3.y, m0.w);  CUPD(eb0.x);

    // main loop: groups of 4, next group prefetched at group top (MLP=5)
#pragma unroll 1
    for (int t0 = 4; t0 < SL; t0 += 4) {
        const int tn0 = (t0 + 4 < SL) ? t0 + 4 : SL - 4;   // clamped reload;
        const float2 nb0 = LD2(tn0);                        // any scalar C2 is
        const float2 nb1 = LD2(tn0 + 1);                    // algebraically exact
        const float2 nb2 = LD2(tn0 + 2);
        const float2 nb3 = LD2(tn0 + 3);
        const int4   nmv = *(const int4*)&mask[b * SL + tn0];

        STEP(1, 0, eb0.x, eb0.y, mv.x);  CUPD(eb1.x);
        STEP(0, 1, eb1.x, eb1.y, mv.y);  CUPD(eb2.x);
        STEP(1, 0, eb2.x, eb2.y, mv.z);  CUPD(eb3.x);
        STEP(0, 1, eb3.x, eb3.y, mv.w);  CUPD(nb0.x);

        eb0 = nb0; eb1 = nb1; eb2 = nb2; eb3 = nb3; mv = nmv;
    }

    // out[b] = Z2*ln2 + ln( sum_j q_j * exp(end_j) )
    float v = qa * fend_a + qb * fend_b;
#pragma unroll
    for (int o = 16; o; o >>= 1) v += __shfl_xor_sync(FULL, v, o);
    if (l == 0) out[b] = fmaf(Z2, LN2, __logf(v));
#undef LD2
}

extern "C" void kernel_launch(void* const* d_in, const int* in_sizes, int n_in,
                              void* d_out, int out_size) {
    const float* emissions = (const float*)d_in[0];
    const int*   msk       = (const int*)d_in[1];
    const float* trans     = (const float*)d_in[2];
    const float* startt    = (const float*)d_in[3];
    const float* endt      = (const float*)d_in[4];
    crf_fwd_kernel<<<NB / 2, 64>>>(emissions, msk, trans, startt, endt, (float*)d_out);
}